// round 1
// baseline (speedup 1.0000x reference)
#include <cuda_runtime.h>

// Trilinear spatial-transformer sampler, degenerate depth axis.
// Output (1,64,64,32). Grid point (oy,ox,k) contributes only when its
// transformed z coordinate lands in [31,33) (image slab lives at depth 32
// of the zero-padded 65-deep volume). z is exactly linear in k, so we
// compute the active k-window analytically and only iterate there.
//
// Faithful details vs the JAX reference:
//  - int casts truncate toward zero ((int) == F2I.RZ == jnp astype(int32))
//  - corner indices clipped to [0,127] BEFORE computing fractional weights
//  - x/y swap: weight fx[i] pairs with row index ys[i], fy[j] with col xs[j]

__global__ __launch_bounds__(256) void stn_kernel(
    const float* __restrict__ img,   // (128,128,32) contiguous
    const float* __restrict__ T,     // 12 floats, row-major 3x4
    float* __restrict__ out,         // (64,64,32)
    int total)
{
    int t = blockIdx.x * 256 + threadIdx.x;
    if (t >= total) return;

    int c   = t & 31;
    int pix = t >> 5;
    int ox  = pix & 63;
    int oy  = (pix >> 6) & 63;

    float xg = fmaf((float)ox, 2.0f / 63.0f, -1.0f);
    float yg = fmaf((float)oy, 2.0f / 63.0f, -1.0f);

    float t0  = __ldg(T + 0),  t1  = __ldg(T + 1),  t2  = __ldg(T + 2),  t3  = __ldg(T + 3);
    float t4  = __ldg(T + 4),  t5  = __ldg(T + 5),  t6  = __ldg(T + 6),  t7  = __ldg(T + 7);
    float t8  = __ldg(T + 8),  t9  = __ldg(T + 9),  t10 = __ldg(T + 10), t11 = __ldg(T + 11);

    // per-pixel base of each transformed coordinate (zg term added per-k)
    float bx = fmaf(t0, xg, fmaf(t1, yg, t3));
    float by = fmaf(t4, xg, fmaf(t5, yg, t7));
    float bz = fmaf(t8, xg, fmaf(t9, yg, t11));

    // Analytic active-k window: z(k) = C + D*k, want z in [31,33).
    // (zg = -1 + k/32 exactly representable; margin ±2 covers fp reassoc.)
    float C = 32.5f * (bz + 1.0f - t10);
    float D = t10 * (65.0f / 64.0f);

    int kLo = 0, kHi = 64;
    if (fabsf(D) > 1e-6f) {
        float k1 = (31.0f - C) / D;
        float k2 = (33.0f - C) / D;
        float lo = fminf(k1, k2), hi = fmaxf(k1, k2);
        lo = fminf(fmaxf(lo, -4.0f), 68.0f);
        hi = fminf(fmaxf(hi, -4.0f), 68.0f);
        kLo = max(0,  (int)floorf(lo) - 2);
        kHi = min(64, (int)ceilf(hi)  + 2);
    } else {
        // z ~ constant in k: either whole range is in-band or none is
        if (C < 29.0f || C > 35.0f) { kHi = -1; }
    }

    float acc = 0.0f;

    #pragma unroll 4
    for (int k = kLo; k <= kHi; ++k) {
        // exact same per-k formula as a naive full loop (band test is exact)
        float zg = fmaf((float)k, 2.0f / 64.0f, -1.0f);
        float sz = fmaf(t10, zg, bz);
        float z  = 0.5f * (sz + 1.0f) * 65.0f;
        int zt = (int)z;  // trunc toward zero
        if (zt != 31 && zt != 32) continue;
        // z0=clip(zt)=32 pairs with fz0 = float(z1)-z = 33-z   (zt==32)
        // z1=clip(zt+1)=32 pairs with fz1 = z-float(z0) = z-31 (zt==31)
        float zw = (zt == 32) ? (33.0f - z) : (z - 31.0f);

        float sx = fmaf(t2, zg, bx);
        float sy = fmaf(t6, zg, by);
        float x = 0.5f * (sx + 1.0f) * 128.0f;
        float y = 0.5f * (sy + 1.0f) * 128.0f;

        int xi = (int)x;   // trunc
        int yi = (int)y;
        int x0 = min(max(xi,     0), 127);
        int x1 = min(max(xi + 1, 0), 127);
        int y0 = min(max(yi,     0), 127);
        int y1 = min(max(yi + 1, 0), 127);

        // weights from CLIPPED corner coords (faithful to reference)
        float fx0 = (float)x1 - x;
        float fx1 = x - (float)x0;
        float fy0 = (float)y1 - y;
        float fy1 = y - (float)y0;

        // x/y swap: fx pairs with row (y) index, fy with col (x) index
        float v00 = __ldg(img + ((y0 * 128 + x0) << 5) + c);  // fx0*fy0
        float v01 = __ldg(img + ((y0 * 128 + x1) << 5) + c);  // fx0*fy1
        float v10 = __ldg(img + ((y1 * 128 + x0) << 5) + c);  // fx1*fy0
        float v11 = __ldg(img + ((y1 * 128 + x1) << 5) + c);  // fx1*fy1

        acc = fmaf(zw, fmaf(fx0, fmaf(fy0, v00, fy1 * v01),
                            fx1 * fmaf(fy0, v10, fy1 * v11)), acc);
    }

    out[t] = acc;
}

extern "C" void kernel_launch(void* const* d_in, const int* in_sizes, int n_in,
                              void* d_out, int out_size)
{
    const float* img = (const float*)d_in[0];   // (1,128,128,32) f32
    const float* T   = (const float*)d_in[1];   // (1,12) f32
    float* out       = (float*)d_out;           // (1,64,64,32) f32

    int total = out_size;                       // 131072
    int blocks = (total + 255) / 256;
    stn_kernel<<<blocks, 256>>>(img, T, out, total);
}